// round 16
// baseline (speedup 1.0000x reference)
#include <cuda_runtime.h>
#include <cuda_fp16.h>
#include <cstdint>

#define N_NODES   50000
#define N_EDGES_C 1600000
#define TILE_E    256
#define NT        512

// Scratch: per-node fp16 [vfeat@W1_recv + 0.5*b1 | vfeat@W1_send + 0.5*b1],
// chunk-major permuted: half index = jc*32 + tg*8 + jj*2 + c  where
// col = 8*(4*jc+jj) + 2*tg + c.  Each (row, jc) chunk is 64 B contiguous.
__device__ __half g_Ph[(size_t)N_NODES * 256];
__device__ unsigned int g_bar;   // monotone ticket barrier (replay-safe)

// ============================ helpers ============================
__device__ __forceinline__ void mma_f16(float* c, const uint32_t* a, uint32_t b0, uint32_t b1) {
    asm volatile("mma.sync.aligned.m16n8k16.row.col.f32.f16.f16.f32 "
        "{%0,%1,%2,%3}, {%4,%5,%6,%7}, {%8,%9}, {%0,%1,%2,%3};"
        : "+f"(c[0]), "+f"(c[1]), "+f"(c[2]), "+f"(c[3])
        : "r"(a[0]), "r"(a[1]), "r"(a[2]), "r"(a[3]), "r"(b0), "r"(b1));
}

__device__ __forceinline__ uint32_t pack_h2(float x, float y) {
    __half2 h = __floats2half2_rn(x, y);
    return *reinterpret_cast<uint32_t*>(&h);
}
__device__ __forceinline__ void wsplit(float w0, float w1, uint32_t& hi, uint32_t& lo) {
    float h0 = __half2float(__float2half_rn(w0));
    float h1 = __half2float(__float2half_rn(w1));
    hi = pack_h2(h0, h1);
    lo = pack_h2(w0 - h0, w1 - h1);
}
__device__ __forceinline__ float2 h2f(uint32_t u) {
    __half2 h = *reinterpret_cast<__half2*>(&u);
    return __half22float2(h);
}

// ---------------------------------------------------------------------------
// Fused persistent kernel.
//  Phase 1: P[n] = vfeat[n] @ W1cat + 0.5*b1, HMMA 3-term fp16, warp-granular
//           work distribution (16 nodes/warp-unit), permuted coalesced stores.
//  Phase-2 weight staging overlapped with the device-wide ticket barrier.
//  Phase 2: edge MLP (R13 config: M=16/warp, 16 warps, fp16 1-term weights).
// ---------------------------------------------------------------------------
__global__ void __launch_bounds__(NT, 1)
fused_kernel(const float* __restrict__ edata,
             const float* __restrict__ vfeat,
             const float* __restrict__ W1,
             const float* __restrict__ b1,
             const float* __restrict__ W2,
             const float* __restrict__ b2,
             const void*  __restrict__ senders,
             const void*  __restrict__ receivers,
             float* __restrict__ out) {
    extern __shared__ char smraw[];
    // Phase 1 view: wc = [32 J][4 s][32 lane] uint4 (64 KB)
    uint4* wc = (uint4*)smraw;
    // Phase 2 view (aliases first 32 KB): w1h, w2h
    uint2* w1h = (uint2*)smraw;              // 16 KB
    uint2* w2h = (uint2*)(w1h + 2048);       // 16 KB
    float* b2f = (float*)(smraw + 65536);    // 64 floats
    int*   sFlag = (int*)(b2f + 64);

    const int tid = threadIdx.x;
    const int wid = tid >> 5, lid = tid & 31;
    const int gq  = lid >> 2;
    const int tg  = lid & 3;

    // =================== Phase 1: precompute P ===================
    for (int idx = tid; idx < 4096; idx += NT) {
        int lane = idx & 31, s = (idx >> 5) & 3, J = idx >> 7;
        int k = 16 * s + 2 * (lane & 3);
        int col = 8 * J + (lane >> 2);
        int r0 = (col < 128) ? (64 + k)  : (128 + k);
        int c0 = (col < 128) ? col : (col - 128);
        uint4 f;
        wsplit(W1[r0 * 128 + c0],       W1[(r0 + 1) * 128 + c0], f.x, f.z);
        wsplit(W1[(r0 + 8) * 128 + c0], W1[(r0 + 9) * 128 + c0], f.y, f.w);
        wc[idx] = f;
    }
    __syncthreads();

    {
        char* Pb = (char*)g_Ph;
        const int NWU = (N_NODES + 15) / 16;           // 3125 warp-units
        const int gw  = blockIdx.x * (NT / 32) + wid;  // global warp id
        const int nwarps = gridDim.x * (NT / 32);
        for (int wu = gw; wu < NWU; wu += nwarps) {
            const int n0 = wu * 16 + gq;
            const int n1 = n0 + 8;
            const int n0c = n0 < N_NODES ? n0 : (N_NODES - 1);
            const int n1c = n1 < N_NODES ? n1 : (N_NODES - 1);

            uint32_t ah[4][4], al[4][4];
            {
                const float* v0 = vfeat + (size_t)n0c * 64;
                const float* v1 = vfeat + (size_t)n1c * 64;
#pragma unroll
                for (int s = 0; s < 4; s++) {
                    int k = 16 * s + 2 * tg;
                    float2 x0 = *(const float2*)(v0 + k);
                    float2 x1 = *(const float2*)(v1 + k);
                    float2 x2 = *(const float2*)(v0 + k + 8);
                    float2 x3 = *(const float2*)(v1 + k + 8);
                    wsplit(x0.x, x0.y, ah[s][0], al[s][0]);
                    wsplit(x1.x, x1.y, ah[s][1], al[s][1]);
                    wsplit(x2.x, x2.y, ah[s][2], al[s][2]);
                    wsplit(x3.x, x3.y, ah[s][3], al[s][3]);
                }
            }

            // Two 128-col halves sequentially (bounds live regs)
#pragma unroll
            for (int h = 0; h < 2; h++) {
                float c[16][4];
#pragma unroll
                for (int J = 0; J < 16; J++) {
                    int col = 8 * (h * 16 + J) + 2 * tg;
                    float bb0 = 0.5f * b1[col & 127];
                    float bb1 = 0.5f * b1[(col + 1) & 127];
                    c[J][0] = bb0; c[J][1] = bb1; c[J][2] = bb0; c[J][3] = bb1;
                }
#pragma unroll
                for (int J = 0; J < 16; J++) {
#pragma unroll
                    for (int s = 0; s < 4; s++) {
                        uint4 f = wc[((h * 16 + J) * 4 + s) * 32 + lid];
                        mma_f16(c[J], ah[s], f.x, f.y);
                        mma_f16(c[J], al[s], f.x, f.y);
                        mma_f16(c[J], ah[s], f.z, f.w);
                    }
                }
#pragma unroll
                for (int jc = 0; jc < 4; jc++) {
                    uint4 u0, u1;
                    uint32_t* p0 = (uint32_t*)&u0;
                    uint32_t* p1 = (uint32_t*)&u1;
#pragma unroll
                    for (int jj = 0; jj < 4; jj++) {
                        int J = 4 * jc + jj;
                        p0[jj] = pack_h2(c[J][0], c[J][1]);
                        p1[jj] = pack_h2(c[J][2], c[J][3]);
                    }
                    uint32_t off = (uint32_t)h * 256u + jc * 64u + tg * 16u;
                    if (n0 < N_NODES) *(uint4*)(Pb + (size_t)n0 * 512 + off) = u0;
                    if (n1 < N_NODES) *(uint4*)(Pb + (size_t)n1 * 512 + off) = u1;
                }
            }
        }
    }

    // ---- Stage phase-2 weights BEFORE the barrier (independent of P) ----
    __syncthreads();   // wc reads done CTA-wide before overwrite
    if (tid < 32) {
        unsigned hiw = ((const unsigned*)senders)[2 * tid + 1];
        unsigned ball = __ballot_sync(0xffffffffu, hiw == 0u);
        if (tid == 0) *sFlag = (ball == 0xffffffffu);
    }
    for (int idx = tid; idx < 2048; idx += NT) {
        int lane = idx & 31, s = (idx >> 5) & 3, j = idx >> 7;
        int k = 16 * s + 2 * (lane & 3);
        int n = 8 * j + (lane >> 2);
        uint2 f;
        f.x = pack_h2(W1[k * 128 + n],       W1[(k + 1) * 128 + n]);
        f.y = pack_h2(W1[(k + 8) * 128 + n], W1[(k + 9) * 128 + n]);
        w1h[idx] = f;
    }
    for (int idx = tid; idx < 2048; idx += NT) {
        int lane = idx & 31, t = (idx >> 5) & 7, j = idx >> 8;
        int k = 16 * t + 2 * (lane & 3);
        int n = 8 * j + (lane >> 2);
        uint2 f;
        f.x = pack_h2(W2[k * 64 + n],       W2[(k + 1) * 64 + n]);
        f.y = pack_h2(W2[(k + 8) * 64 + n], W2[(k + 9) * 64 + n]);
        w2h[idx] = f;
    }
    if (tid < 64) b2f[tid] = b2[tid];

    // =================== Device-wide barrier ===================
    __threadfence();          // make this CTA's P stores visible device-wide
    __syncthreads();          // all threads arrived (stores issued)
    if (tid == 0) {
        unsigned int ticket = atomicAdd(&g_bar, 1u);
        unsigned int target = (ticket / (unsigned)gridDim.x + 1u) * (unsigned)gridDim.x;
        volatile unsigned int* vb = &g_bar;
        while (*vb < target) { __nanosleep(64); }
    }
    __syncthreads();
    __threadfence();          // acquire: other CTAs' P stores visible to us

    // =================== Phase 2: edge MLP ===================
    const int idx64 = *sFlag;
    const long long* r64 = (const long long*)receivers;
    const int*       r32 = (const int*)receivers;
    const long long* s64 = (const long long*)senders;
    const int*       s32 = (const int*)senders;

    const char* Pbase = (const char*)g_Ph;
    const int ntiles = (N_EDGES_C + TILE_E - 1) / TILE_E;   // 6250 exact

    for (int tile = blockIdx.x; tile < ntiles; tile += gridDim.x) {
        const int base = tile * TILE_E + wid * 16 + gq;
        const int em0 = base, em1 = base + 8;
        const int e0c = em0 < N_EDGES_C ? em0 : (N_EDGES_C - 1);
        const int e1c = em1 < N_EDGES_C ? em1 : (N_EDGES_C - 1);

        uint32_t offR0, offS0, offR1, offS1;
        {
            int rr0 = idx64 ? (int)r64[e0c] : r32[e0c];
            int ss0 = idx64 ? (int)s64[e0c] : s32[e0c];
            int rr1 = idx64 ? (int)r64[e1c] : r32[e1c];
            int ss1 = idx64 ? (int)s64[e1c] : s32[e1c];
            offR0 = (uint32_t)rr0 * 512u + tg * 16u;
            offS0 = (uint32_t)ss0 * 512u + 256u + tg * 16u;
            offR1 = (uint32_t)rr1 * 512u + tg * 16u;
            offS1 = (uint32_t)ss1 * 512u + 256u + tg * 16u;
        }

        uint32_t a1[4][4];
        {
            const float* x0 = edata + (size_t)e0c * 64;
            const float* x1 = edata + (size_t)e1c * 64;
#pragma unroll
            for (int s = 0; s < 4; s++) {
                int k = 16 * s + 2 * tg;
                float2 v0 = *(const float2*)(x0 + k);
                float2 v1 = *(const float2*)(x1 + k);
                float2 v2 = *(const float2*)(x0 + k + 8);
                float2 v3 = *(const float2*)(x1 + k + 8);
                a1[s][0] = pack_h2(v0.x, v0.y);
                a1[s][1] = pack_h2(v1.x, v1.y);
                a1[s][2] = pack_h2(v2.x, v2.y);
                a1[s][3] = pack_h2(v3.x, v3.y);
            }
        }

        uint32_t a2[8][4];
#pragma unroll
        for (int jc = 0; jc < 4; jc++) {
            float c1[4][4];
            {
                uint4 ra = *(const uint4*)(Pbase + offR0 + jc * 64);
                uint4 sa = *(const uint4*)(Pbase + offS0 + jc * 64);
                uint4 rb = *(const uint4*)(Pbase + offR1 + jc * 64);
                uint4 sb = *(const uint4*)(Pbase + offS1 + jc * 64);
                const uint32_t* raw = (const uint32_t*)&ra;
                const uint32_t* saw = (const uint32_t*)&sa;
                const uint32_t* rbw = (const uint32_t*)&rb;
                const uint32_t* sbw = (const uint32_t*)&sb;
#pragma unroll
                for (int jj = 0; jj < 4; jj++) {
                    float2 fa = h2f(raw[jj]), fb = h2f(saw[jj]);
                    float2 fc = h2f(rbw[jj]), fd = h2f(sbw[jj]);
                    c1[jj][0] = fa.x + fb.x;
                    c1[jj][1] = fa.y + fb.y;
                    c1[jj][2] = fc.x + fd.x;
                    c1[jj][3] = fc.y + fd.y;
                }
            }
#pragma unroll
            for (int jj = 0; jj < 4; jj++) {
                int J = 4 * jc + jj;
#pragma unroll
                for (int s = 0; s < 4; s++) {
                    uint2 f = w1h[(J * 4 + s) * 32 + lid];
                    mma_f16(c1[jj], a1[s], f.x, f.y);
                }
            }
#pragma unroll
            for (int p = 0; p < 2; p++) {
                int t = 2 * jc + p;
                a2[t][0] = pack_h2(fmaxf(c1[2 * p][0], 0.0f),     fmaxf(c1[2 * p][1], 0.0f));
                a2[t][1] = pack_h2(fmaxf(c1[2 * p][2], 0.0f),     fmaxf(c1[2 * p][3], 0.0f));
                a2[t][2] = pack_h2(fmaxf(c1[2 * p + 1][0], 0.0f), fmaxf(c1[2 * p + 1][1], 0.0f));
                a2[t][3] = pack_h2(fmaxf(c1[2 * p + 1][2], 0.0f), fmaxf(c1[2 * p + 1][3], 0.0f));
            }
        }

#pragma unroll
        for (int jh = 0; jh < 2; jh++) {
            float d2[4][4];
#pragma unroll
            for (int jj = 0; jj < 4; jj++) {
                int j = 4 * jh + jj;
                float2 bb = *(const float2*)(b2f + 8 * j + 2 * tg);
                d2[jj][0] = bb.x; d2[jj][1] = bb.y;
                d2[jj][2] = bb.x; d2[jj][3] = bb.y;
            }
#pragma unroll
            for (int jj = 0; jj < 4; jj++) {
                int j = 4 * jh + jj;
#pragma unroll
                for (int t = 0; t < 8; t++) {
                    uint2 f = w2h[(j * 8 + t) * 32 + lid];
                    mma_f16(d2[jj], a2[t], f.x, f.y);
                }
            }
            if (em0 < N_EDGES_C) {
                float* o0 = out + (size_t)em0 * 64 + 32 * jh;
#pragma unroll
                for (int jj = 0; jj < 4; jj++)
                    *(float2*)(o0 + 8 * jj + 2 * tg) = make_float2(d2[jj][0], d2[jj][1]);
            }
            if (em1 < N_EDGES_C) {
                float* o1 = out + (size_t)em1 * 64 + 32 * jh;
#pragma unroll
                for (int jj = 0; jj < 4; jj++)
                    *(float2*)(o1 + 8 * jj + 2 * tg) = make_float2(d2[jj][2], d2[jj][3]);
            }
        }
    }
}

// ---------------------------------------------------------------------------
extern "C" void kernel_launch(void* const* d_in, const int* in_sizes, int n_in,
                              void* d_out, int out_size) {
    const float* edata     = (const float*)d_in[0];
    const float* vfeat     = (const float*)d_in[1];
    const float* W1        = (const float*)d_in[2];
    const float* b1        = (const float*)d_in[3];
    const float* W2        = (const float*)d_in[4];
    const float* b2        = (const float*)d_in[5];
    const void*  senders   = d_in[6];
    const void*  receivers = d_in[7];
    float* out = (float*)d_out;
    (void)in_sizes; (void)n_in; (void)out_size;

    const int f_smem = 65536 + 64 * 4 + 16;   // 65808 B

    cudaFuncSetAttribute(fused_kernel,
                         cudaFuncAttributeMaxDynamicSharedMemorySize, f_smem);

    int sms = 0;
    cudaDeviceGetAttribute(&sms, cudaDevAttrMultiProcessorCount, 0);
    if (sms <= 0) sms = 148;

    fused_kernel<<<sms, NT, f_smem>>>(edata, vfeat, W1, b1, W2, b2,
                                      senders, receivers, out);
}

// round 17
// speedup vs baseline: 1.0137x; 1.0137x over previous
#include <cuda_runtime.h>
#include <cuda_fp16.h>
#include <cstdint>

#define N_NODES   50000
#define N_EDGES_C 1600000
#define TILE_E    256
#define NT        512

// Scratch: per-node fp16 [vfeat@W1_recv + 0.5*b1 | vfeat@W1_send + 0.5*b1],
// chunk-major permuted: half index = jc*32 + tg*8 + jj*2 + c  where
// col = 8*(4*jc+jj) + 2*tg + c.  Each (row, jc) chunk is 64 B contiguous.
__device__ __half g_Ph[(size_t)N_NODES * 256];
__device__ unsigned int g_bar;   // monotone ticket barrier (replay-safe)

// ============================ helpers ============================
__device__ __forceinline__ void mma_f16(float* c, const uint32_t* a, uint32_t b0, uint32_t b1) {
    asm volatile("mma.sync.aligned.m16n8k16.row.col.f32.f16.f16.f32 "
        "{%0,%1,%2,%3}, {%4,%5,%6,%7}, {%8,%9}, {%0,%1,%2,%3};"
        : "+f"(c[0]), "+f"(c[1]), "+f"(c[2]), "+f"(c[3])
        : "r"(a[0]), "r"(a[1]), "r"(a[2]), "r"(a[3]), "r"(b0), "r"(b1));
}

__device__ __forceinline__ uint32_t pack_h2(float x, float y) {
    __half2 h = __floats2half2_rn(x, y);
    return *reinterpret_cast<uint32_t*>(&h);
}
__device__ __forceinline__ void wsplit(float w0, float w1, uint32_t& hi, uint32_t& lo) {
    float h0 = __half2float(__float2half_rn(w0));
    float h1 = __half2float(__float2half_rn(w1));
    hi = pack_h2(h0, h1);
    lo = pack_h2(w0 - h0, w1 - h1);
}
__device__ __forceinline__ float2 h2f(uint32_t u) {
    __half2 h = *reinterpret_cast<__half2*>(&u);
    return __half22float2(h);
}

// ---------------------------------------------------------------------------
// Fused persistent kernel.
//  Phase 1: P[n] = vfeat[n] @ W1cat + 0.5*b1, HMMA 3-term fp16, warp-granular
//           distribution, permuted coalesced stores.
//  Phase-2 weight staging (PAIRED uint4 fragments) overlapped with barrier.
//  Phase 2: edge MLP, M=16/warp, 16 warps, fp16 1-term weights; each LDS.128
//           feeds TWO mmas (J-pairs for W1, t-pairs for W2).
// ---------------------------------------------------------------------------
__global__ void __launch_bounds__(NT, 1)
fused_kernel(const float* __restrict__ edata,
             const float* __restrict__ vfeat,
             const float* __restrict__ W1,
             const float* __restrict__ b1,
             const float* __restrict__ W2,
             const float* __restrict__ b2,
             const void*  __restrict__ senders,
             const void*  __restrict__ receivers,
             float* __restrict__ out) {
    extern __shared__ char smraw[];
    // Phase 1 view: wc = [32 J][4 s][32 lane] uint4 (64 KB)
    uint4* wc = (uint4*)smraw;
    // Phase 2 view (aliases first 32 KB): paired fragments
    uint4* w1q = (uint4*)smraw;              // [8 Jp][4 s][32 lane]  16 KB
    uint4* w2q = w1q + 1024;                 // [8 j][4 tp][32 lane]  16 KB
    float* b2f = (float*)(smraw + 65536);    // 64 floats
    int*   sFlag = (int*)(b2f + 64);

    const int tid = threadIdx.x;
    const int wid = tid >> 5, lid = tid & 31;
    const int gq  = lid >> 2;
    const int tg  = lid & 3;

    // =================== Phase 1: precompute P ===================
    for (int idx = tid; idx < 4096; idx += NT) {
        int lane = idx & 31, s = (idx >> 5) & 3, J = idx >> 7;
        int k = 16 * s + 2 * (lane & 3);
        int col = 8 * J + (lane >> 2);
        int r0 = (col < 128) ? (64 + k)  : (128 + k);
        int c0 = (col < 128) ? col : (col - 128);
        uint4 f;
        wsplit(W1[r0 * 128 + c0],       W1[(r0 + 1) * 128 + c0], f.x, f.z);
        wsplit(W1[(r0 + 8) * 128 + c0], W1[(r0 + 9) * 128 + c0], f.y, f.w);
        wc[idx] = f;
    }
    __syncthreads();

    {
        char* Pb = (char*)g_Ph;
        const int NWU = (N_NODES + 15) / 16;           // 3125 warp-units
        const int gw  = blockIdx.x * (NT / 32) + wid;
        const int nwarps = gridDim.x * (NT / 32);
        for (int wu = gw; wu < NWU; wu += nwarps) {
            const int n0 = wu * 16 + gq;
            const int n1 = n0 + 8;
            const int n0c = n0 < N_NODES ? n0 : (N_NODES - 1);
            const int n1c = n1 < N_NODES ? n1 : (N_NODES - 1);

            uint32_t ah[4][4], al[4][4];
            {
                const float* v0 = vfeat + (size_t)n0c * 64;
                const float* v1 = vfeat + (size_t)n1c * 64;
#pragma unroll
                for (int s = 0; s < 4; s++) {
                    int k = 16 * s + 2 * tg;
                    float2 x0 = *(const float2*)(v0 + k);
                    float2 x1 = *(const float2*)(v1 + k);
                    float2 x2 = *(const float2*)(v0 + k + 8);
                    float2 x3 = *(const float2*)(v1 + k + 8);
                    wsplit(x0.x, x0.y, ah[s][0], al[s][0]);
                    wsplit(x1.x, x1.y, ah[s][1], al[s][1]);
                    wsplit(x2.x, x2.y, ah[s][2], al[s][2]);
                    wsplit(x3.x, x3.y, ah[s][3], al[s][3]);
                }
            }

#pragma unroll
            for (int h = 0; h < 2; h++) {
                float c[16][4];
#pragma unroll
                for (int J = 0; J < 16; J++) {
                    int col = 8 * (h * 16 + J) + 2 * tg;
                    float bb0 = 0.5f * b1[col & 127];
                    float bb1 = 0.5f * b1[(col + 1) & 127];
                    c[J][0] = bb0; c[J][1] = bb1; c[J][2] = bb0; c[J][3] = bb1;
                }
#pragma unroll
                for (int J = 0; J < 16; J++) {
#pragma unroll
                    for (int s = 0; s < 4; s++) {
                        uint4 f = wc[((h * 16 + J) * 4 + s) * 32 + lid];
                        mma_f16(c[J], ah[s], f.x, f.y);
                        mma_f16(c[J], al[s], f.x, f.y);
                        mma_f16(c[J], ah[s], f.z, f.w);
                    }
                }
#pragma unroll
                for (int jc = 0; jc < 4; jc++) {
                    uint4 u0, u1;
                    uint32_t* p0 = (uint32_t*)&u0;
                    uint32_t* p1 = (uint32_t*)&u1;
#pragma unroll
                    for (int jj = 0; jj < 4; jj++) {
                        int J = 4 * jc + jj;
                        p0[jj] = pack_h2(c[J][0], c[J][1]);
                        p1[jj] = pack_h2(c[J][2], c[J][3]);
                    }
                    uint32_t off = (uint32_t)h * 256u + jc * 64u + tg * 16u;
                    if (n0 < N_NODES) *(uint4*)(Pb + (size_t)n0 * 512 + off) = u0;
                    if (n1 < N_NODES) *(uint4*)(Pb + (size_t)n1 * 512 + off) = u1;
                }
            }
        }
    }

    // ---- Stage phase-2 weights BEFORE the barrier (paired layout) ----
    __syncthreads();   // wc reads done CTA-wide before overwrite
    if (tid < 32) {
        unsigned hiw = ((const unsigned*)senders)[2 * tid + 1];
        unsigned ball = __ballot_sync(0xffffffffu, hiw == 0u);
        if (tid == 0) *sFlag = (ball == 0xffffffffu);
    }
    // W1 paired: entry (Jp, s, lane) = {J0-frag, J1-frag}, J0=2Jp, J1=2Jp+1
    for (int idx = tid; idx < 1024; idx += NT) {
        int lane = idx & 31, s = (idx >> 5) & 3, Jp = idx >> 7;
        int k = 16 * s + 2 * (lane & 3);
        int n0 = 8 * (2 * Jp)     + (lane >> 2);
        int n1 = 8 * (2 * Jp + 1) + (lane >> 2);
        uint4 f;
        f.x = pack_h2(W1[k * 128 + n0],       W1[(k + 1) * 128 + n0]);
        f.y = pack_h2(W1[(k + 8) * 128 + n0], W1[(k + 9) * 128 + n0]);
        f.z = pack_h2(W1[k * 128 + n1],       W1[(k + 1) * 128 + n1]);
        f.w = pack_h2(W1[(k + 8) * 128 + n1], W1[(k + 9) * 128 + n1]);
        w1q[idx] = f;
    }
    // W2 paired: entry (j, tp, lane) = {t0-frag, t1-frag}, t0=2tp, t1=2tp+1
    for (int idx = tid; idx < 1024; idx += NT) {
        int lane = idx & 31, tp = (idx >> 5) & 3, j = idx >> 7;
        int k0 = 16 * (2 * tp)     + 2 * (lane & 3);
        int k1 = 16 * (2 * tp + 1) + 2 * (lane & 3);
        int n = 8 * j + (lane >> 2);
        uint4 f;
        f.x = pack_h2(W2[k0 * 64 + n],       W2[(k0 + 1) * 64 + n]);
        f.y = pack_h2(W2[(k0 + 8) * 64 + n], W2[(k0 + 9) * 64 + n]);
        f.z = pack_h2(W2[k1 * 64 + n],       W2[(k1 + 1) * 64 + n]);
        f.w = pack_h2(W2[(k1 + 8) * 64 + n], W2[(k1 + 9) * 64 + n]);
        w2q[idx] = f;
    }
    if (tid < 64) b2f[tid] = b2[tid];

    // =================== Device-wide barrier ===================
    __threadfence();
    __syncthreads();
    if (tid == 0) {
        unsigned int ticket = atomicAdd(&g_bar, 1u);
        unsigned int target = (ticket / (unsigned)gridDim.x + 1u) * (unsigned)gridDim.x;
        volatile unsigned int* vb = &g_bar;
        while (*vb < target) { __nanosleep(64); }
    }
    __syncthreads();
    __threadfence();

    // =================== Phase 2: edge MLP ===================
    const int idx64 = *sFlag;
    const long long* r64 = (const long long*)receivers;
    const int*       r32 = (const int*)receivers;
    const long long* s64 = (const long long*)senders;
    const int*       s32 = (const int*)senders;

    const char* Pbase = (const char*)g_Ph;
    const int ntiles = (N_EDGES_C + TILE_E - 1) / TILE_E;   // 6250 exact

    for (int tile = blockIdx.x; tile < ntiles; tile += gridDim.x) {
        const int base = tile * TILE_E + wid * 16 + gq;
        const int em0 = base, em1 = base + 8;
        const int e0c = em0 < N_EDGES_C ? em0 : (N_EDGES_C - 1);
        const int e1c = em1 < N_EDGES_C ? em1 : (N_EDGES_C - 1);

        uint32_t offR0, offS0, offR1, offS1;
        {
            int rr0 = idx64 ? (int)r64[e0c] : r32[e0c];
            int ss0 = idx64 ? (int)s64[e0c] : s32[e0c];
            int rr1 = idx64 ? (int)r64[e1c] : r32[e1c];
            int ss1 = idx64 ? (int)s64[e1c] : s32[e1c];
            offR0 = (uint32_t)rr0 * 512u + tg * 16u;
            offS0 = (uint32_t)ss0 * 512u + 256u + tg * 16u;
            offR1 = (uint32_t)rr1 * 512u + tg * 16u;
            offS1 = (uint32_t)ss1 * 512u + 256u + tg * 16u;
        }

        uint32_t a1[4][4];
        {
            const float* x0 = edata + (size_t)e0c * 64;
            const float* x1 = edata + (size_t)e1c * 64;
#pragma unroll
            for (int s = 0; s < 4; s++) {
                int k = 16 * s + 2 * tg;
                float2 v0 = *(const float2*)(x0 + k);
                float2 v1 = *(const float2*)(x1 + k);
                float2 v2 = *(const float2*)(x0 + k + 8);
                float2 v3 = *(const float2*)(x1 + k + 8);
                a1[s][0] = pack_h2(v0.x, v0.y);
                a1[s][1] = pack_h2(v1.x, v1.y);
                a1[s][2] = pack_h2(v2.x, v2.y);
                a1[s][3] = pack_h2(v3.x, v3.y);
            }
        }

        // GEMM1 in 4 chunks of 4 J (paired fragment loads); produce A2 frags
        uint32_t a2[8][4];
#pragma unroll
        for (int jc = 0; jc < 4; jc++) {
            float c1[4][4];
            {
                uint4 ra = *(const uint4*)(Pbase + offR0 + jc * 64);
                uint4 sa = *(const uint4*)(Pbase + offS0 + jc * 64);
                uint4 rb = *(const uint4*)(Pbase + offR1 + jc * 64);
                uint4 sb = *(const uint4*)(Pbase + offS1 + jc * 64);
                const uint32_t* raw = (const uint32_t*)&ra;
                const uint32_t* saw = (const uint32_t*)&sa;
                const uint32_t* rbw = (const uint32_t*)&rb;
                const uint32_t* sbw = (const uint32_t*)&sb;
#pragma unroll
                for (int jj = 0; jj < 4; jj++) {
                    float2 fa = h2f(raw[jj]), fb = h2f(saw[jj]);
                    float2 fc = h2f(rbw[jj]), fd = h2f(sbw[jj]);
                    c1[jj][0] = fa.x + fb.x;
                    c1[jj][1] = fa.y + fb.y;
                    c1[jj][2] = fc.x + fd.x;
                    c1[jj][3] = fc.y + fd.y;
                }
            }
            // paired: Jp = 2*jc + jjp covers J = 4*jc + 2*jjp (+1)
#pragma unroll
            for (int jjp = 0; jjp < 2; jjp++) {
#pragma unroll
                for (int s = 0; s < 4; s++) {
                    uint4 f = w1q[((2 * jc + jjp) * 4 + s) * 32 + lid];
                    mma_f16(c1[2 * jjp],     a1[s], f.x, f.y);
                    mma_f16(c1[2 * jjp + 1], a1[s], f.z, f.w);
                }
            }
#pragma unroll
            for (int p = 0; p < 2; p++) {
                int t = 2 * jc + p;
                a2[t][0] = pack_h2(fmaxf(c1[2 * p][0], 0.0f),     fmaxf(c1[2 * p][1], 0.0f));
                a2[t][1] = pack_h2(fmaxf(c1[2 * p][2], 0.0f),     fmaxf(c1[2 * p][3], 0.0f));
                a2[t][2] = pack_h2(fmaxf(c1[2 * p + 1][0], 0.0f), fmaxf(c1[2 * p + 1][1], 0.0f));
                a2[t][3] = pack_h2(fmaxf(c1[2 * p + 1][2], 0.0f), fmaxf(c1[2 * p + 1][3], 0.0f));
            }
        }

        // GEMM2 (single-term, paired t loads) in 2 halves of 4 j
#pragma unroll
        for (int jh = 0; jh < 2; jh++) {
            float d2[4][4];
#pragma unroll
            for (int jj = 0; jj < 4; jj++) {
                int j = 4 * jh + jj;
                float2 bb = *(const float2*)(b2f + 8 * j + 2 * tg);
                d2[jj][0] = bb.x; d2[jj][1] = bb.y;
                d2[jj][2] = bb.x; d2[jj][3] = bb.y;
            }
#pragma unroll
            for (int jj = 0; jj < 4; jj++) {
                int j = 4 * jh + jj;
#pragma unroll
                for (int tp = 0; tp < 4; tp++) {
                    uint4 f = w2q[(j * 4 + tp) * 32 + lid];
                    mma_f16(d2[jj], a2[2 * tp],     f.x, f.y);
                    mma_f16(d2[jj], a2[2 * tp + 1], f.z, f.w);
                }
            }
            if (em0 < N_EDGES_C) {
                float* o0 = out + (size_t)em0 * 64 + 32 * jh;
#pragma unroll
                for (int jj = 0; jj < 4; jj++)
                    *(float2*)(o0 + 8 * jj + 2 * tg) = make_float2(d2[jj][0], d2[jj][1]);
            }
            if (em1 < N_EDGES_C) {
                float* o1 = out + (size_t)em1 * 64 + 32 * jh;
#pragma unroll
                for (int jj = 0; jj < 4; jj++)
                    *(float2*)(o1 + 8 * jj + 2 * tg) = make_float2(d2[jj][2], d2[jj][3]);
            }
        }
    }
}

// ---------------------------------------------------------------------------
extern "C" void kernel_launch(void* const* d_in, const int* in_sizes, int n_in,
                              void* d_out, int out_size) {
    const float* edata     = (const float*)d_in[0];
    const float* vfeat     = (const float*)d_in[1];
    const float* W1        = (const float*)d_in[2];
    const float* b1        = (const float*)d_in[3];
    const float* W2        = (const float*)d_in[4];
    const float* b2        = (const float*)d_in[5];
    const void*  senders   = d_in[6];
    const void*  receivers = d_in[7];
    float* out = (float*)d_out;
    (void)in_sizes; (void)n_in; (void)out_size;

    const int f_smem = 65536 + 64 * 4 + 16;   // 65808 B

    cudaFuncSetAttribute(fused_kernel,
                         cudaFuncAttributeMaxDynamicSharedMemorySize, f_smem);

    int sms = 0;
    cudaDeviceGetAttribute(&sms, cudaDevAttrMultiProcessorCount, 0);
    if (sms <= 0) sms = 148;

    fused_kernel<<<sms, NT, f_smem>>>(edata, vfeat, W1, b1, W2, b2,
                                      senders, receivers, out);
}